// round 2
// baseline (speedup 1.0000x reference)
#include <cuda_runtime.h>

// UniSURF-style renderer: per-ray sphere intersect + 32-step occupancy march
// + 8 secant iterations on a tiny MLP (3 -> 32 -> 1).
//
// Restructurings vs. the reference:
//   occ logit z(d) = b2 + sum_j relu(A_j + d * R_j) * W2_j
//     A_j = cam.W1_j + b1_j   (per-launch, from shared)
//     R_j = ray.W1_j          (per-ray, registers)
//   Coarse march uses only sign(z)  (sigmoid(z)-0.5 < 0  <=>  z < 0).
//   Packed fp32x2 FMAs (Blackwell FFMA2) halve FMA-pipe instruction count.
//   Early break at first crossing; rays missing the sphere skip all MLP work.

#define HID     32
#define NPAIR   16
#define NSTEPS  32
#define NSECANT 8
#define NEARV   0.5f
#define EPSV    1e-6f

typedef unsigned long long ull;

__device__ __forceinline__ ull pack2(float x, float y) {
    ull r;
    asm("mov.b64 %0, {%1, %2};" : "=l"(r) : "f"(x), "f"(y));
    return r;
}

__device__ __forceinline__ void unpack2(ull v, float& x, float& y) {
    asm("mov.b64 {%0, %1}, %2;" : "=f"(x), "=f"(y) : "l"(v));
}

// one hidden-unit pair: acc += relu(A + d*R) * W   (packed fp32x2)
__device__ __forceinline__ ull pair_step(ull dd, ull R, ull A, ull W, ull acc) {
    ull x;
    asm("fma.rn.f32x2 %0, %1, %2, %3;" : "=l"(x) : "l"(dd), "l"(R), "l"(A));
    float x0, x1;
    unpack2(x, x0, x1);
    x0 = fmaxf(x0, 0.0f);
    x1 = fmaxf(x1, 0.0f);
    ull h = pack2(x0, x1);
    ull out;
    asm("fma.rn.f32x2 %0, %1, %2, %3;" : "=l"(out) : "l"(h), "l"(W), "l"(acc));
    return out;
}

__device__ __forceinline__ float occ_z(float d, const ull* R, const ull* A,
                                       const ull* W, float b2v) {
    ull dd;
    asm("mov.b64 %0, {%1, %1};" : "=l"(dd) : "f"(d));
    ull acc0 = 0ull, acc1 = 0ull, acc2 = 0ull, acc3 = 0ull;  // (0.0f, 0.0f)
#pragma unroll
    for (int k = 0; k < NPAIR; k += 4) {
        acc0 = pair_step(dd, R[k + 0], A[k + 0], W[k + 0], acc0);
        acc1 = pair_step(dd, R[k + 1], A[k + 1], W[k + 1], acc1);
        acc2 = pair_step(dd, R[k + 2], A[k + 2], W[k + 2], acc2);
        acc3 = pair_step(dd, R[k + 3], A[k + 3], W[k + 3], acc3);
    }
    ull s01, s23, s;
    asm("add.rn.f32x2 %0, %1, %2;" : "=l"(s01) : "l"(acc0), "l"(acc1));
    asm("add.rn.f32x2 %0, %1, %2;" : "=l"(s23) : "l"(acc2), "l"(acc3));
    asm("add.rn.f32x2 %0, %1, %2;" : "=l"(s)   : "l"(s01),  "l"(s23));
    float sx, sy;
    unpack2(s, sx, sy);
    return b2v + sx + sy;
}

__device__ __forceinline__ float sigmoidf_(float z) {
    return 1.0f / (1.0f + __expf(-z));
}

__global__ void __launch_bounds__(128) unisurf_kernel(
    const float* __restrict__ cam, const float* __restrict__ dirs,
    const float* __restrict__ W1, const float* __restrict__ b1,
    const float* __restrict__ W2, const float* __restrict__ b2,
    float* __restrict__ out, int P)
{
    __shared__ float sW1[3][HID];
    __shared__ float sA[HID];
    __shared__ float sW2[HID];
    __shared__ float sMisc[5];  // cam0..2, b2, |cam|^2

    const int tid = threadIdx.x;
    if (tid < HID) {
        const float c0 = cam[0], c1 = cam[1], c2 = cam[2];
        const float w0 = W1[tid], w1 = W1[HID + tid], w2 = W1[2 * HID + tid];
        sW1[0][tid] = w0;
        sW1[1][tid] = w1;
        sW1[2][tid] = w2;
        sA[tid] = fmaf(c0, w0, fmaf(c1, w1, fmaf(c2, w2, b1[tid])));
        sW2[tid] = W2[tid];
        if (tid == 0) {
            sMisc[0] = c0; sMisc[1] = c1; sMisc[2] = c2;
            sMisc[3] = b2[0];
            sMisc[4] = c0 * c0 + c1 * c1 + c2 * c2;
        }
    }
    __syncthreads();

    const int p = blockIdx.x * blockDim.x + tid;
    if (p >= P) return;

    const float dx = dirs[3 * p + 0];
    const float dy = dirs[3 * p + 1];
    const float dz = dirs[3 * p + 2];
    const float invn = rsqrtf(dx * dx + dy * dy + dz * dz);
    const float rx = dx * invn, ry = dy * invn, rz = dz * invn;

    const float c0 = sMisc[0], c1 = sMisc[1], c2 = sMisc[2];
    const float b2v = sMisc[3], cc = sMisc[4];

    const float rcd = rx * c0 + ry * c1 + rz * c2;
    const float under = rcd * rcd - (cc - 1.0f);  // radius = 1

    float dpred = 0.0f, osurf = 0.0f;

    if (under > 0.0f) {
        const float s = sqrtf(under);
        const float far = fmaxf(s - rcd, NEARV + EPSV);

        // per-ray MLP operands, packed as fp32x2 pairs
        ull R[NPAIR], A[NPAIR], W[NPAIR];
#pragma unroll
        for (int k = 0; k < NPAIR; k++) {
            const int j = 2 * k;
            const float r0 = fmaf(rx, sW1[0][j],
                             fmaf(ry, sW1[1][j], rz * sW1[2][j]));
            const float r1 = fmaf(rx, sW1[0][j + 1],
                             fmaf(ry, sW1[1][j + 1], rz * sW1[2][j + 1]));
            R[k] = pack2(r0, r1);
            A[k] = pack2(sA[j], sA[j + 1]);
            W[k] = pack2(sW2[j], sW2[j + 1]);
        }

        // coarse march: find first z<0 -> z>=0 crossing, break early
        const float stepc = 1.0f / (float)(NSTEPS - 1);
        float zprev = occ_z(NEARV, R, A, W, b2v);  // t=0 -> d=NEAR exactly
        float dprev = NEARV;
        bool  found = false;
        float dl = 0.0f, dh = 0.0f, zl = 0.0f, zh = 0.0f;

#pragma unroll 1
        for (int i = 1; i < NSTEPS; i++) {
            const float t = (float)i * stepc;
            const float dcur = fmaf(far, t, NEARV * (1.0f - t));
            const float z = occ_z(dcur, R, A, W, b2v);
            if (zprev < 0.0f && z >= 0.0f) {
                found = true;
                dl = dprev; dh = dcur; zl = zprev; zh = z;
                break;
            }
            zprev = z;
            dprev = dcur;
        }

        if (found) {
            float fl = sigmoidf_(zl) - 0.5f;
            float fh = sigmoidf_(zh) - 0.5f;
#pragma unroll 1
            for (int it = 0; it < NSECANT; it++) {
                float den = fh - fl;
                if (fabsf(den) < EPSV) den = EPSV;
                const float dm = dl - fl * (dh - dl) / den;
                const float fm = sigmoidf_(occ_z(dm, R, A, W, b2v)) - 0.5f;
                if (fm < 0.0f) { dl = dm; fl = fm; }
                else           { dh = dm; fh = fm; }
            }
            float den = fh - fl;
            if (fabsf(den) < EPSV) den = EPSV;
            dpred = dl - fl * (dh - dl) / den;
            osurf = sigmoidf_(occ_z(dpred, R, A, W, b2v));
        }
    }

    out[p] = dpred;
    out[P + p] = osurf;
}

extern "C" void kernel_launch(void* const* d_in, const int* in_sizes, int n_in,
                              void* d_out, int out_size)
{
    const float* cam  = (const float*)d_in[0];
    const float* dirs = (const float*)d_in[1];
    const float* W1   = (const float*)d_in[2];
    const float* b1   = (const float*)d_in[3];
    const float* W2   = (const float*)d_in[4];
    const float* b2   = (const float*)d_in[5];
    float* out = (float*)d_out;

    const int P = in_sizes[1] / 3;
    const int threads = 128;
    const int blocks = (P + threads - 1) / threads;
    unisurf_kernel<<<blocks, threads>>>(cam, dirs, W1, b1, W2, b2, out, P);
}

// round 4
// speedup vs baseline: 1.0168x; 1.0168x over previous
#include <cuda_runtime.h>

// UniSURF-style renderer: per-ray sphere intersect + 32-step occupancy march
// + 8 secant iterations on a tiny MLP (3 -> 32 -> 1).
//
//   occ logit z(d) = b2 + sum_j relu(A_j + d * R_j) * W2_j
//     A_j = cam.W1_j + b1_j   (per-launch), R_j = ray.W1_j (per-ray)
//   Coarse march uses only sign(z)  (sigmoid(z)-0.5 < 0  <=>  z < 0).
//   Packed fp32x2 FMAs; branchless march (crossing bitmask + __ffs);
//   balanced persistent-style grid (4 blocks x 148 SMs, one wave).

#define HID     32
#define NPAIR   16
#define NSTEPS  32
#define NSECANT 8
#define NEARV   0.5f
#define EPSV    1e-6f
#define NBLK    592          // 4 blocks/SM x 148 SMs (sm_100a)

typedef unsigned long long ull;

__device__ __forceinline__ ull pack2(float x, float y) {
    ull r;
    asm("mov.b64 %0, {%1, %2};" : "=l"(r) : "f"(x), "f"(y));
    return r;
}

__device__ __forceinline__ void unpack2(ull v, float& x, float& y) {
    asm("mov.b64 {%0, %1}, %2;" : "=f"(x), "=f"(y) : "l"(v));
}

// one hidden-unit pair: acc += relu(A + d*R) * W   (packed fp32x2)
__device__ __forceinline__ ull pair_step(ull dd, ull R, ull A, ull W, ull acc) {
    ull x;
    asm("fma.rn.f32x2 %0, %1, %2, %3;" : "=l"(x) : "l"(dd), "l"(R), "l"(A));
    float x0, x1;
    unpack2(x, x0, x1);
    x0 = fmaxf(x0, 0.0f);
    x1 = fmaxf(x1, 0.0f);
    ull h = pack2(x0, x1);
    ull out;
    asm("fma.rn.f32x2 %0, %1, %2, %3;" : "=l"(out) : "l"(h), "l"(W), "l"(acc));
    return out;
}

__device__ __forceinline__ float occ_z(float d, const ull* R, const ull* A,
                                       const ull* W, float b2v) {
    ull dd;
    asm("mov.b64 %0, {%1, %1};" : "=l"(dd) : "f"(d));
    ull acc0 = 0ull, acc1 = 0ull, acc2 = 0ull, acc3 = 0ull;  // (0.0f, 0.0f)
#pragma unroll
    for (int k = 0; k < NPAIR; k += 4) {
        acc0 = pair_step(dd, R[k + 0], A[k + 0], W[k + 0], acc0);
        acc1 = pair_step(dd, R[k + 1], A[k + 1], W[k + 1], acc1);
        acc2 = pair_step(dd, R[k + 2], A[k + 2], W[k + 2], acc2);
        acc3 = pair_step(dd, R[k + 3], A[k + 3], W[k + 3], acc3);
    }
    ull s01, s23, s;
    asm("add.rn.f32x2 %0, %1, %2;" : "=l"(s01) : "l"(acc0), "l"(acc1));
    asm("add.rn.f32x2 %0, %1, %2;" : "=l"(s23) : "l"(acc2), "l"(acc3));
    asm("add.rn.f32x2 %0, %1, %2;" : "=l"(s)   : "l"(s01),  "l"(s23));
    float sx, sy;
    unpack2(s, sx, sy);
    return b2v + sx + sy;
}

__device__ __forceinline__ float sigmoidf_(float z) {
    return 1.0f / (1.0f + __expf(-z));
}

__global__ void __launch_bounds__(128, 4) unisurf_kernel(
    const float* __restrict__ cam, const float* __restrict__ dirs,
    const float* __restrict__ W1, const float* __restrict__ b1,
    const float* __restrict__ W2, const float* __restrict__ b2,
    float* __restrict__ out, int P)
{
    __shared__ float sW1[3][HID];
    __shared__ float sA[HID];
    __shared__ float sW2[HID];
    __shared__ float sMisc[5];  // cam0..2, b2, |cam|^2

    const int tid = threadIdx.x;
    if (tid < HID) {
        const float c0 = cam[0], c1 = cam[1], c2 = cam[2];
        const float w0 = W1[tid], w1 = W1[HID + tid], w2 = W1[2 * HID + tid];
        sW1[0][tid] = w0;
        sW1[1][tid] = w1;
        sW1[2][tid] = w2;
        sA[tid] = fmaf(c0, w0, fmaf(c1, w1, fmaf(c2, w2, b1[tid])));
        sW2[tid] = W2[tid];
        if (tid == 0) {
            sMisc[0] = c0; sMisc[1] = c1; sMisc[2] = c2;
            sMisc[3] = b2[0];
            sMisc[4] = c0 * c0 + c1 * c1 + c2 * c2;
        }
    }
    __syncthreads();

    // balanced contiguous range for this block (single full wave)
    const int nb = gridDim.x;
    const int b  = blockIdx.x;
    const int beg = (int)(((long long)b * P) / nb);
    const int end = (int)(((long long)(b + 1) * P) / nb);

    const float c0 = sMisc[0], c1 = sMisc[1], c2 = sMisc[2];
    const float b2v = sMisc[3], cc = sMisc[4];
    const float stepc = 1.0f / (float)(NSTEPS - 1);

    for (int p = beg + tid; p < end; p += blockDim.x) {
        const float dx = dirs[3 * p + 0];
        const float dy = dirs[3 * p + 1];
        const float dz = dirs[3 * p + 2];
        const float invn = rsqrtf(dx * dx + dy * dy + dz * dz);
        const float rx = dx * invn, ry = dy * invn, rz = dz * invn;

        const float rcd = rx * c0 + ry * c1 + rz * c2;
        const float under = rcd * rcd - (cc - 1.0f);  // radius = 1

        float dpred = 0.0f, osurf = 0.0f;

        if (under > 0.0f) {
            const float s = sqrtf(under);
            const float far = fmaxf(s - rcd, NEARV + EPSV);

            // per-ray MLP operands, packed as fp32x2 pairs
            ull R[NPAIR], A[NPAIR], W[NPAIR];
#pragma unroll
            for (int k = 0; k < NPAIR; k++) {
                const int j = 2 * k;
                const float r0 = fmaf(rx, sW1[0][j],
                                 fmaf(ry, sW1[1][j], rz * sW1[2][j]));
                const float r1 = fmaf(rx, sW1[0][j + 1],
                                 fmaf(ry, sW1[1][j + 1], rz * sW1[2][j + 1]));
                R[k] = pack2(r0, r1);
                A[k] = pack2(sA[j], sA[j + 1]);
                W[k] = pack2(sW2[j], sW2[j + 1]);
            }

            // branchless coarse march: bitmask of free->occupied crossings
            unsigned mask = 0u;
            float zprev = occ_z(NEARV, R, A, W, b2v);  // t=0 -> d=NEAR
#pragma unroll 1
            for (int i = 1; i < NSTEPS; i++) {
                const float t = (float)i * stepc;
                const float dcur = fmaf(far, t, NEARV * (1.0f - t));
                const float z = occ_z(dcur, R, A, W, b2v);
                const bool cross = (zprev < 0.0f) && (z >= 0.0f);
                mask |= (cross ? 1u : 0u) << (i - 1);
                zprev = z;
            }

            if (mask) {
                const int idx = __ffs(mask) - 1;  // first crossing segment
                const float tl = (float)idx * stepc;
                const float th = (float)(idx + 1) * stepc;
                float dl = fmaf(far, tl, NEARV * (1.0f - tl));
                float dh = fmaf(far, th, NEARV * (1.0f - th));
                float fl = sigmoidf_(occ_z(dl, R, A, W, b2v)) - 0.5f;
                float fh = sigmoidf_(occ_z(dh, R, A, W, b2v)) - 0.5f;

#pragma unroll 1
                for (int it = 0; it < NSECANT; it++) {
                    float den = fh - fl;
                    if (fabsf(den) < EPSV) den = EPSV;
                    const float dm = dl - __fdividef(fl * (dh - dl), den);
                    const float fm =
                        sigmoidf_(occ_z(dm, R, A, W, b2v)) - 0.5f;
                    if (fm < 0.0f) { dl = dm; fl = fm; }
                    else           { dh = dm; fh = fm; }
                }
                float den = fh - fl;
                if (fabsf(den) < EPSV) den = EPSV;
                dpred = dl - __fdividef(fl * (dh - dl), den);
                osurf = sigmoidf_(occ_z(dpred, R, A, W, b2v));
            }
        }

        out[p] = dpred;
        out[P + p] = osurf;
    }
}

extern "C" void kernel_launch(void* const* d_in, const int* in_sizes, int n_in,
                              void* d_out, int out_size)
{
    const float* cam  = (const float*)d_in[0];
    const float* dirs = (const float*)d_in[1];
    const float* W1   = (const float*)d_in[2];
    const float* b1   = (const float*)d_in[3];
    const float* W2   = (const float*)d_in[4];
    const float* b2   = (const float*)d_in[5];
    float* out = (float*)d_out;

    const int P = in_sizes[1] / 3;
    const int threads = 128;
    int blocks = NBLK;
    const int maxb = (P + threads - 1) / threads;
    if (blocks > maxb) blocks = maxb;
    unisurf_kernel<<<blocks, threads>>>(cam, dirs, W1, b1, W2, b2, out, P);
}